// round 2
// baseline (speedup 1.0000x reference)
#include <cuda_runtime.h>
#include <math.h>

// Problem dims (fixed by the dataset)
#define NI 4096
#define NH 8192
#define NO 2048

// ---------------- device scratch (allocation-free) ----------------
__device__ float g_base_h[NH];   // inputs@W_i2h.T + outputs0@W_o2h.T  (loop-invariant)
__device__ float g_base_o[NO];   // inputs@W_i2o.T + outputs0@W_o2o.T
__device__ float g_act_a[NH];    // ping-pong hidden state
__device__ float g_act_b[NH];
__device__ int   g_flags[3];     // [0]=activs0 nonzero, [1]=outputs0 nonzero, [2]=always 1

// ---------------- helpers ----------------
__device__ __forceinline__ float apply_act(float x, int id) {
    switch (id) {
        case 0:  return x;                                   // identity
        case 1:  return x >= 0.f ? x : 0.01f * x;            // leaky_relu
        case 2:  return fmaxf(x, 0.f);                       // relu
        case 3:  return 1.f / (1.f + expf(-x));              // sigmoid
        default: return tanhf(x);                            // tanh
    }
}

// Per-warp dot(W_row, x) over K elements. K must be a multiple of 512
// (float4 * 32 lanes * 4-way unroll). Holds for K in {2048, 4096, 8192}.
__device__ __forceinline__ float warp_dot(const float* __restrict__ Wrow,
                                          const float* __restrict__ x,
                                          int K, int lane) {
    const float4* __restrict__ w4 = reinterpret_cast<const float4*>(Wrow);
    const float4* __restrict__ x4 = reinterpret_cast<const float4*>(x);
    const int n4 = K >> 2;
    float s0 = 0.f, s1 = 0.f, s2 = 0.f, s3 = 0.f;
    for (int i = lane; i < n4; i += 128) {
        float4 a0 = w4[i];       float4 b0 = x4[i];
        float4 a1 = w4[i + 32];  float4 b1 = x4[i + 32];
        float4 a2 = w4[i + 64];  float4 b2 = x4[i + 64];
        float4 a3 = w4[i + 96];  float4 b3 = x4[i + 96];
        s0 += a0.x*b0.x + a0.y*b0.y + a0.z*b0.z + a0.w*b0.w;
        s1 += a1.x*b1.x + a1.y*b1.y + a1.z*b1.z + a1.w*b1.w;
        s2 += a2.x*b2.x + a2.y*b2.y + a2.z*b2.z + a2.w*b2.w;
        s3 += a3.x*b3.x + a3.y*b3.y + a3.z*b3.z + a3.w*b3.w;
    }
    return (s0 + s1) + (s2 + s3);
}

__device__ __forceinline__ float warp_reduce(float s) {
    #pragma unroll
    for (int off = 16; off; off >>= 1)
        s += __shfl_xor_sync(0xffffffffu, s, off);
    return s;
}

// ---------------- kernels ----------------

// block 0 scans activs0, block 1 scans outputs0; writes nonzero flags.
__global__ void flag_kernel(const float* __restrict__ act0,
                            const float* __restrict__ out0) {
    const float* p = (blockIdx.x == 0) ? act0 : out0;
    const int    n = (blockIdx.x == 0) ? NH : NO;
    int any = 0;
    for (int i = threadIdx.x; i < n; i += blockDim.x)
        any |= (p[i] != 0.f);
    any = __syncthreads_or(any);
    if (threadIdx.x == 0) {
        g_flags[blockIdx.x] = any;
        g_flags[2] = 1;
    }
}

// base[row] = dot(Wx[row], x) + (flag ? dot(Wo[row], o) : 0)
__global__ void base_kernel(const float* __restrict__ Wx, const float* __restrict__ x, int Kx,
                            const float* __restrict__ Wo, const float* __restrict__ o, int Ko,
                            float* __restrict__ base, int M, int flag_idx) {
    const int row  = (blockIdx.x * blockDim.x + threadIdx.x) >> 5;
    const int lane = threadIdx.x & 31;
    if (row >= M) return;
    float s = warp_dot(Wx + (size_t)row * Kx, x, Kx, lane);
    if (g_flags[flag_idx])
        s += warp_dot(Wo + (size_t)row * Ko, o, Ko, lane);
    s = warp_reduce(s);
    if (lane == 0) base[row] = s;
}

// y[row] = act( resp[row] * (base[row] + (flag ? dot(W[row], x) : 0)) + bias[row] )
__global__ void gemv_act_kernel(const float* __restrict__ W, const float* __restrict__ x, int K,
                                const float* __restrict__ base,
                                const float* __restrict__ resp,
                                const float* __restrict__ bias,
                                const int*   __restrict__ ids,
                                float* __restrict__ y, int M, int flag_idx) {
    const int row  = (blockIdx.x * blockDim.x + threadIdx.x) >> 5;
    const int lane = threadIdx.x & 31;
    if (row >= M) return;
    float s = 0.f;
    if (g_flags[flag_idx])
        s = warp_dot(W + (size_t)row * K, x, K, lane);
    s = warp_reduce(s);
    if (lane == 0) {
        float pre = resp[row] * (base[row] + s) + bias[row];
        y[row] = apply_act(pre, ids[row]);
    }
}

// ---------------- launch ----------------
extern "C" void kernel_launch(void* const* d_in, const int* in_sizes, int n_in,
                              void* d_out, int out_size) {
    const float* inputs   = (const float*)d_in[0];
    const float* W_i2h    = (const float*)d_in[1];
    const float* W_h2h    = (const float*)d_in[2];
    const float* W_o2h    = (const float*)d_in[3];
    const float* W_i2o    = (const float*)d_in[4];
    const float* W_h2o    = (const float*)d_in[5];
    const float* W_o2o    = (const float*)d_in[6];
    const float* h_resp   = (const float*)d_in[7];
    const float* h_bias   = (const float*)d_in[8];
    const float* o_resp   = (const float*)d_in[9];
    const float* o_bias   = (const float*)d_in[10];
    const float* activs0  = (const float*)d_in[11];
    const float* outputs0 = (const float*)d_in[12];
    const int*   h_ids    = (const int*)d_in[13];
    const int*   o_ids    = (const int*)d_in[14];
    float* out = (float*)d_out;

    // Resolve device-symbol addresses once per process (static init happens on
    // the first, non-captured correctness call; values are stable thereafter).
    static float *base_h = nullptr, *base_o, *act_a, *act_b;
    if (!base_h) {
        cudaGetSymbolAddress((void**)&base_h, g_base_h);
        cudaGetSymbolAddress((void**)&base_o, g_base_o);
        cudaGetSymbolAddress((void**)&act_a,  g_act_a);
        cudaGetSymbolAddress((void**)&act_b,  g_act_b);
    }

    const int THREADS = 256;                 // 8 warps = 8 rows per block
    const int BLK_NH  = NH / 8;              // 1024 blocks
    const int BLK_NO  = NO / 8;              // 256 blocks

    // 0. zero-vector flags from the actual input buffers (fully general)
    flag_kernel<<<2, THREADS>>>(activs0, outputs0);

    // 1. loop-invariant parts (computed ONCE, not per step)
    base_kernel<<<BLK_NH, THREADS>>>(W_i2h, inputs, NI, W_o2h, outputs0, NO,
                                     base_h, NH, /*flag=*/1);
    base_kernel<<<BLK_NO, THREADS>>>(W_i2o, inputs, NI, W_o2o, outputs0, NO,
                                     base_o, NO, /*flag=*/1);

    // 2. three recurrent hidden steps (step 1 skips W_h2h if activs0 == 0)
    gemv_act_kernel<<<BLK_NH, THREADS>>>(W_h2h, activs0, NH, base_h,
                                         h_resp, h_bias, h_ids, act_a, NH, /*flag=*/0);
    gemv_act_kernel<<<BLK_NH, THREADS>>>(W_h2h, act_a, NH, base_h,
                                         h_resp, h_bias, h_ids, act_b, NH, /*flag=*/2);
    gemv_act_kernel<<<BLK_NH, THREADS>>>(W_h2h, act_b, NH, base_h,
                                         h_resp, h_bias, h_ids, act_a, NH, /*flag=*/2);

    // 3. output layer
    gemv_act_kernel<<<BLK_NO, THREADS>>>(W_h2o, act_a, NH, base_o,
                                         o_resp, o_bias, o_ids, out, NO, /*flag=*/2);
}